// round 15
// baseline (speedup 1.0000x reference)
#include <cuda_runtime.h>
#include <cuda_fp16.h>
#include <math.h>
#include <stdint.h>
#include <string.h>

#define BB     16
#define NN     1024
#define DIMV   384
#define DEPTH  6
#define HEADS  6
#define DH     64
#define INNER  384
#define MLPV   1536
#define ROWS   (BB*NN)       // 16384
#define BHN    (BB*HEADS)    // 96
#define QKVW   (3*INNER)     // 1152
#define NEGMAX -3.4028234663852886e38f

// ---------------- scratch (half precision operands) ----------------
__device__ __half g_ln[(size_t)ROWS * DIMV];
__device__ __half g_qkv[(size_t)ROWS * QKVW];
__device__ __half g_attn[(size_t)ROWS * INNER];
__device__ __half g_ff[(size_t)ROWS * MLPV];
// half copies of weights, NATURAL [K][N] layout
#define WT_QKV_OFF  0
#define WT_QKV_PER  (DIMV*QKVW)
#define WT_WO_OFF   (WT_QKV_OFF + DEPTH*WT_QKV_PER)
#define WT_WO_PER   (INNER*DIMV)
#define WT_W1_OFF   (WT_WO_OFF + DEPTH*WT_WO_PER)
#define WT_W1_PER   (DIMV*MLPV)
#define WT_W2_OFF   (WT_W1_OFF + DEPTH*WT_W1_PER)
#define WT_W2_PER   (MLPV*DIMV)
#define WT_TOTAL    (WT_W2_OFF + DEPTH*WT_W2_PER)
__device__ __half g_wh[(size_t)WT_TOTAL];

// ================= helpers =================
__device__ __forceinline__ uint32_t smem_u32(const void* p) {
    uint32_t r;
    asm("{ .reg .u64 t; cvta.to.shared.u64 t, %1; cvt.u32.u64 %0, t; }" : "=r"(r) : "l"(p));
    return r;
}
__device__ __forceinline__ void cp16(uint32_t dst, const void* src) {
    asm volatile("cp.async.cg.shared.global [%0], [%1], 16;" :: "r"(dst), "l"(src));
}
__device__ __forceinline__ void mma16(float c[4], const uint32_t a[4], const uint32_t b[2]) {
    asm volatile(
        "mma.sync.aligned.m16n8k16.row.col.f32.f16.f16.f32 "
        "{%0,%1,%2,%3}, {%4,%5,%6,%7}, {%8,%9}, {%0,%1,%2,%3};"
        : "+f"(c[0]), "+f"(c[1]), "+f"(c[2]), "+f"(c[3])
        : "r"(a[0]), "r"(a[1]), "r"(a[2]), "r"(a[3]), "r"(b[0]), "r"(b[1]));
}
__device__ __forceinline__ void ldm_x4(uint32_t r[4], uint32_t a) {
    asm volatile("ldmatrix.sync.aligned.m8n8.x4.shared.b16 {%0,%1,%2,%3}, [%4];"
                 : "=r"(r[0]), "=r"(r[1]), "=r"(r[2]), "=r"(r[3]) : "r"(a));
}
__device__ __forceinline__ void ldm_x2(uint32_t r[2], uint32_t a) {
    asm volatile("ldmatrix.sync.aligned.m8n8.x2.shared.b16 {%0,%1}, [%2];"
                 : "=r"(r[0]), "=r"(r[1]) : "r"(a));
}
__device__ __forceinline__ void ldm_x2t(uint32_t r[2], uint32_t a) {
    asm volatile("ldmatrix.sync.aligned.m8n8.x2.trans.shared.b16 {%0,%1}, [%2];"
                 : "=r"(r[0]), "=r"(r[1]) : "r"(a));
}
__device__ __forceinline__ uint32_t packh2(float x, float y) {
    __half2 h = __floats2half2_rn(x, y);
    uint32_t u;
    memcpy(&u, &h, 4);
    return u;
}

// ================= dense fp16 GEMM, 128x128 tile ====================
// EPI 0: C(half)=AB ; EPI 2: C(half)=gelu(AB+bias) ; EPI 3: C(half)=AB, q-cols scaled
#define GS_A_B      18432u
#define GS_STAGE_B  35840u
#define GS_BYTES    (3u * GS_STAGE_B)         // 107520 B
template <int EPI>
__global__ void __launch_bounds__(256, 2) mma_gemm(
    const __half* __restrict__ A, const __half* __restrict__ Bw,
    const float* __restrict__ bias, const float* __restrict__ temp, int layer,
    void* __restrict__ Cv, int M, int Nn, int K) {
    extern __shared__ __align__(16) char smraw[];
    const int tid = threadIdx.x;
    const int wid = tid >> 5, lane = tid & 31;
    const int g = lane >> 2, tg = lane & 3;
    const int l16 = lane & 15;
    const int wm = (wid & 1) * 64, wn = (wid >> 1) * 32;
    const int m0 = blockIdx.y * 128, n0 = blockIdx.x * 128;

    float qs = 1.0f;
    if (EPI == 3) qs = expf(temp[layer]);

    float c[4][4][4];
    #pragma unroll
    for (int mt = 0; mt < 4; ++mt)
        #pragma unroll
        for (int nt = 0; nt < 4; ++nt)
            #pragma unroll
            for (int k = 0; k < 4; ++k) c[mt][nt][k] = 0.0f;

    const int nc = K >> 6;
    const uint32_t sbase = smem_u32(smraw);

    auto issue = [&](int ci) {
        uint32_t base = sbase + (uint32_t)(ci % 3) * GS_STAGE_B;
        int kt = ci << 6;
        #pragma unroll
        for (int i = 0; i < 4; ++i) {
            int f = tid + i * 256;
            int r = f >> 3, c8 = (f & 7) << 3;
            cp16(base + (uint32_t)(r * 72 + c8) * 2u,
                 A + (size_t)(m0 + r) * K + kt + c8);
        }
        #pragma unroll
        for (int i = 0; i < 4; ++i) {
            int f = tid + i * 256;
            int r = f >> 4, c8 = (f & 15) << 3;
            cp16(base + GS_A_B + (uint32_t)(r * 136 + c8) * 2u,
                 Bw + (size_t)(kt + r) * Nn + n0 + c8);
        }
        asm volatile("cp.async.commit_group;" ::: "memory");
    };

    issue(0);
    issue(1);

    for (int ci = 0; ci < nc; ++ci) {
        asm volatile("cp.async.wait_group 1;" ::: "memory");
        __syncthreads();
        if (ci + 2 < nc) {
            issue(ci + 2);
        } else {
            asm volatile("cp.async.commit_group;" ::: "memory");
        }

        const uint32_t stA = sbase + (uint32_t)(ci % 3) * GS_STAGE_B;
        const uint32_t stB = stA + GS_A_B;
        #pragma unroll
        for (int ks = 0; ks < 4; ++ks) {
            uint32_t af[4][4], bf[4][2];
            #pragma unroll
            for (int mt = 0; mt < 4; ++mt)
                ldm_x4(af[mt], stA + (uint32_t)((wm + mt * 16 + l16) * 72
                                                + ks * 16 + (lane >> 4) * 8) * 2u);
            #pragma unroll
            for (int nt = 0; nt < 4; ++nt)
                ldm_x2t(bf[nt], stB + (uint32_t)((ks * 16 + l16) * 136
                                                 + wn + nt * 8) * 2u);
            #pragma unroll
            for (int mt = 0; mt < 4; ++mt)
                #pragma unroll
                for (int nt = 0; nt < 4; ++nt)
                    mma16(c[mt][nt], af[mt], bf[nt]);
        }
    }

    #pragma unroll
    for (int mt = 0; mt < 4; ++mt) {
        #pragma unroll
        for (int nt = 0; nt < 4; ++nt) {
            int col = n0 + wn + nt * 8 + 2 * tg;
            float sc = (EPI == 3 && col < INNER) ? qs : 1.0f;
            #pragma unroll
            for (int h = 0; h < 2; ++h) {
                int row = m0 + wm + mt * 16 + g + h * 8;
                float v0 = c[mt][nt][h * 2 + 0];
                float v1 = c[mt][nt][h * 2 + 1];
                if (EPI == 2) {
                    v0 += bias[col]; v1 += bias[col + 1];
                    v0 = 0.5f * v0 * (1.0f + erff(v0 * 0.70710678118654752f));
                    v1 = 0.5f * v1 * (1.0f + erff(v1 * 0.70710678118654752f));
                }
                if (EPI == 3) { v0 *= sc; v1 *= sc; }
                *(__half2*)((__half*)Cv + (size_t)row * Nn + col) =
                    __floats2half2_rn(v0, v1);
            }
        }
    }
}

// ================= dense fp16 GEMM, 64x128 tile (residual epilogue) =================
// For N=384 outputs (proj, FF2): finer M-split -> better wave balance.
// 256 thr = 8 warps (2m x 4n), warp tile 32x32. C(f32) = res + AB + bias.
#define G6_A_B      9216u                      // A 64x72 halves
#define G6_STAGE_B  26624u                     // + B 64x136 halves (17408)
#define G6_BYTES    (3u * G6_STAGE_B)          // 79872 B
__global__ void __launch_bounds__(256, 2) mma_gemm64(
    const __half* __restrict__ A, const __half* __restrict__ Bw,
    const float* __restrict__ bias, const float* __restrict__ res,
    float* __restrict__ C, int M, int Nn, int K) {
    extern __shared__ __align__(16) char smraw[];
    const int tid = threadIdx.x;
    const int wid = tid >> 5, lane = tid & 31;
    const int g = lane >> 2, tg = lane & 3;
    const int l16 = lane & 15;
    const int wm = (wid & 1) * 32, wn = (wid >> 1) * 32;
    const int m0 = blockIdx.y * 64, n0 = blockIdx.x * 128;

    float c[2][4][4];
    #pragma unroll
    for (int mt = 0; mt < 2; ++mt)
        #pragma unroll
        for (int nt = 0; nt < 4; ++nt)
            #pragma unroll
            for (int k = 0; k < 4; ++k) c[mt][nt][k] = 0.0f;

    const int nc = K >> 6;
    const uint32_t sbase = smem_u32(smraw);

    auto issue = [&](int ci) {
        uint32_t base = sbase + (uint32_t)(ci % 3) * G6_STAGE_B;
        int kt = ci << 6;
        #pragma unroll
        for (int i = 0; i < 2; ++i) {          // A: 64 rows x 64 halves
            int f = tid + i * 256;
            int r = f >> 3, c8 = (f & 7) << 3;
            cp16(base + (uint32_t)(r * 72 + c8) * 2u,
                 A + (size_t)(m0 + r) * K + kt + c8);
        }
        #pragma unroll
        for (int i = 0; i < 4; ++i) {          // B: 64 k-rows x 128 halves
            int f = tid + i * 256;
            int r = f >> 4, c8 = (f & 15) << 3;
            cp16(base + G6_A_B + (uint32_t)(r * 136 + c8) * 2u,
                 Bw + (size_t)(kt + r) * Nn + n0 + c8);
        }
        asm volatile("cp.async.commit_group;" ::: "memory");
    };

    issue(0);
    issue(1);

    for (int ci = 0; ci < nc; ++ci) {
        asm volatile("cp.async.wait_group 1;" ::: "memory");
        __syncthreads();
        if (ci + 2 < nc) {
            issue(ci + 2);
        } else {
            asm volatile("cp.async.commit_group;" ::: "memory");
        }

        const uint32_t stA = sbase + (uint32_t)(ci % 3) * G6_STAGE_B;
        const uint32_t stB = stA + G6_A_B;
        #pragma unroll
        for (int ks = 0; ks < 4; ++ks) {
            uint32_t af[2][4], bf[4][2];
            #pragma unroll
            for (int mt = 0; mt < 2; ++mt)
                ldm_x4(af[mt], stA + (uint32_t)((wm + mt * 16 + l16) * 72
                                                + ks * 16 + (lane >> 4) * 8) * 2u);
            #pragma unroll
            for (int nt = 0; nt < 4; ++nt)
                ldm_x2t(bf[nt], stB + (uint32_t)((ks * 16 + l16) * 136
                                                 + wn + nt * 8) * 2u);
            #pragma unroll
            for (int mt = 0; mt < 2; ++mt)
                #pragma unroll
                for (int nt = 0; nt < 4; ++nt)
                    mma16(c[mt][nt], af[mt], bf[nt]);
        }
    }

    #pragma unroll
    for (int mt = 0; mt < 2; ++mt) {
        #pragma unroll
        for (int nt = 0; nt < 4; ++nt) {
            int col = n0 + wn + nt * 8 + 2 * tg;
            #pragma unroll
            for (int h = 0; h < 2; ++h) {
                int row = m0 + wm + mt * 16 + g + h * 8;
                float v0 = c[mt][nt][h * 2 + 0] + bias[col];
                float v1 = c[mt][nt][h * 2 + 1] + bias[col + 1];
                float2 r2 = *(const float2*)(res + (size_t)row * Nn + col);
                v0 += r2.x; v1 += r2.y;
                *(float2*)(C + (size_t)row * Nn + col) = make_float2(v0, v1);
            }
        }
    }
}

// ================= flash attention: pre-scaled Q, no-max softmax ====================
#define FL_PS_H    (128 * 72)
#define FL_KV_H    (64 * 72)
#define FL_TOT_H   (FL_PS_H + 6 * FL_KV_H)    // 36864
#define FL_DSMEM   (FL_TOT_H * 2)             // 73728 B
__global__ void __launch_bounds__(256, 2) flash_kernel(
    const __half* __restrict__ qkv,
    __half* __restrict__ o) {
    extern __shared__ __align__(16) __half fsh[];

    int bh = blockIdx.y;
    int b = bh / HEADS, h = bh - b * HEADS;
    int rt = blockIdx.x * 128;
    int tid = threadIdx.x, wid = tid >> 5, lane = tid & 31;
    int g = lane >> 2, tg = lane & 3;
    int l16 = lane & 15;

    const __half* qb = qkv + (size_t)b * NN * QKVW + h * DH;
    const __half* kb = qb + INNER;
    const __half* vb = qb + 2 * INNER;
    const uint32_t sbase = smem_u32(fsh);

    #pragma unroll
    for (int i = 0; i < 4; ++i) {
        int f = tid + i * 256;
        int r = f >> 3, c8 = (f & 7) << 3;
        *(uint4*)&fsh[r * 72 + c8] = *(const uint4*)(qb + (size_t)(rt + r) * QKVW + c8);
    }
    auto issue_kv = [&](int i) {
        uint32_t kbb = sbase + (uint32_t)(FL_PS_H + (i % 3) * 2 * FL_KV_H) * 2u;
        uint32_t vbb = kbb + FL_KV_H * 2u;
        int kt = i << 6;
        #pragma unroll
        for (int it = 0; it < 2; ++it) {
            int f = tid + it * 256;
            int r = f >> 3, c8 = (f & 7) << 3;
            cp16(kbb + (uint32_t)(r * 72 + c8) * 2u, kb + (size_t)(kt + r) * QKVW + c8);
            cp16(vbb + (uint32_t)(r * 72 + c8) * 2u, vb + (size_t)(kt + r) * QKVW + c8);
        }
        asm volatile("cp.async.commit_group;" ::: "memory");
    };
    issue_kv(0);
    issue_kv(1);
    __syncthreads();

    uint32_t qf[4][4];
    #pragma unroll
    for (int ks = 0; ks < 4; ++ks)
        ldm_x4(qf[ks], sbase + (uint32_t)((wid * 16 + l16) * 72
                                          + ks * 16 + (lane >> 4) * 8) * 2u);

    float l0 = 0.0f, l1 = 0.0f;
    float oacc[8][4];
    #pragma unroll
    for (int nt = 0; nt < 8; ++nt)
        #pragma unroll
        for (int k = 0; k < 4; ++k) oacc[nt][k] = 0.0f;

    const int gi0 = rt + wid * 16 + g;
    const int gi1 = gi0 + 8;

    for (int i = 0; i < NN / 64; ++i) {
        asm volatile("cp.async.wait_group 1;" ::: "memory");
        __syncthreads();
        if (i + 2 < NN / 64) {
            issue_kv(i + 2);
        } else {
            asm volatile("cp.async.commit_group;" ::: "memory");
        }

        const uint32_t kbb = sbase + (uint32_t)(FL_PS_H + (i % 3) * 2 * FL_KV_H) * 2u;
        const uint32_t vbb = kbb + FL_KV_H * 2u;
        const int kt = i << 6;

        float s[8][4];
        #pragma unroll
        for (int nt = 0; nt < 8; ++nt)
            #pragma unroll
            for (int k = 0; k < 4; ++k) s[nt][k] = 0.0f;
        #pragma unroll
        for (int ks = 0; ks < 4; ++ks) {
            #pragma unroll
            for (int nt = 0; nt < 8; ++nt) {
                uint32_t bf[2];
                ldm_x2(bf, kbb + (uint32_t)((nt * 8 + (l16 & 7)) * 72
                                            + ks * 16 + (l16 >> 3) * 8) * 2u);
                mma16(s[nt], qf[ks], bf);
            }
        }
        // P = exp(S) (Q pre-scaled; scores O(1)); diagonal -> 0
        float sum0 = 0.0f, sum1 = 0.0f;
        #pragma unroll
        for (int nt = 0; nt < 8; ++nt) {
            int gj = kt + nt * 8 + 2 * tg;
            s[nt][0] = (gi0 == gj)     ? 0.0f : __expf(s[nt][0]);
            s[nt][1] = (gi0 == gj + 1) ? 0.0f : __expf(s[nt][1]);
            s[nt][2] = (gi1 == gj)     ? 0.0f : __expf(s[nt][2]);
            s[nt][3] = (gi1 == gj + 1) ? 0.0f : __expf(s[nt][3]);
            sum0 += s[nt][0] + s[nt][1];
            sum1 += s[nt][2] + s[nt][3];
        }
        sum0 += __shfl_xor_sync(0xffffffffu, sum0, 1);
        sum0 += __shfl_xor_sync(0xffffffffu, sum0, 2);
        sum1 += __shfl_xor_sync(0xffffffffu, sum1, 1);
        sum1 += __shfl_xor_sync(0xffffffffu, sum1, 2);
        l0 += sum0;
        l1 += sum1;
        #pragma unroll
        for (int ks = 0; ks < 4; ++ks) {
            uint32_t pf[4];
            pf[0] = packh2(s[2 * ks][0],     s[2 * ks][1]);
            pf[1] = packh2(s[2 * ks][2],     s[2 * ks][3]);
            pf[2] = packh2(s[2 * ks + 1][0], s[2 * ks + 1][1]);
            pf[3] = packh2(s[2 * ks + 1][2], s[2 * ks + 1][3]);
            #pragma unroll
            for (int nt = 0; nt < 8; ++nt) {
                uint32_t bf[2];
                ldm_x2t(bf, vbb + (uint32_t)((ks * 16 + l16) * 72 + nt * 8) * 2u);
                mma16(oacc[nt], pf, bf);
            }
        }
    }

    float inv0 = 1.0f / l0, inv1 = 1.0f / l1;
    #pragma unroll
    for (int nt = 0; nt < 8; ++nt) {
        int gc = h * DH + nt * 8 + 2 * tg;
        int gr0 = b * NN + gi0;
        int gr1 = b * NN + gi1;
        *(__half2*)(o + (size_t)gr0 * INNER + gc) =
            __floats2half2_rn(oacc[nt][0] * inv0, oacc[nt][1] * inv0);
        *(__half2*)(o + (size_t)gr1 * INNER + gc) =
            __floats2half2_rn(oacc[nt][2] * inv1, oacc[nt][3] * inv1);
    }
}

// ---------------- fused fp32 -> half convert ----------------
__global__ void cvt_all_kernel(const float* __restrict__ s0, int n0,
                               const float* __restrict__ s1, int n1,
                               const float* __restrict__ s2, int n2,
                               const float* __restrict__ s3,
                               __half* __restrict__ dst, int n4tot) {
    int i = blockIdx.x * blockDim.x + threadIdx.x;
    if (i >= n4tot) return;
    int e = i * 4;
    const float* src;
    if (e < n0)                 { src = s0 + e; }
    else if (e < n0 + n1)       { src = s1 + (e - n0); }
    else if (e < n0 + n1 + n2)  { src = s2 + (e - n0 - n1); }
    else                        { src = s3 + (e - n0 - n1 - n2); }
    float4 v = *(const float4*)src;
    __half2 h0 = __floats2half2_rn(v.x, v.y);
    __half2 h1 = __floats2half2_rn(v.z, v.w);
    uint32_t u0, u1;
    memcpy(&u0, &h0, 4); memcpy(&u1, &h1, 4);
    uint2 ov; ov.x = u0; ov.y = u1;
    *(uint2*)(dst + (size_t)e) = ov;
}

// ---------------- LayerNorm: one WARP per row ----------------
__global__ void ln_kernel(const float* __restrict__ x,
                          const float* __restrict__ gamma,
                          const float* __restrict__ beta,
                          __half* __restrict__ y) {
    int wid = threadIdx.x >> 5, lane = threadIdx.x & 31;
    int row = blockIdx.x * 8 + wid;
    const float* xr = x + (size_t)row * DIMV;
    __half*      yr = y + (size_t)row * DIMV;

    float4 v[3];
    #pragma unroll
    for (int j = 0; j < 3; ++j)
        v[j] = *(const float4*)(xr + j * 128 + lane * 4);

    float s = 0.0f, q = 0.0f;
    #pragma unroll
    for (int j = 0; j < 3; ++j) {
        s += v[j].x + v[j].y + v[j].z + v[j].w;
        q += v[j].x * v[j].x + v[j].y * v[j].y + v[j].z * v[j].z + v[j].w * v[j].w;
    }
    #pragma unroll
    for (int o = 16; o > 0; o >>= 1) {
        s += __shfl_xor_sync(0xffffffffu, s, o);
        q += __shfl_xor_sync(0xffffffffu, q, o);
    }
    float m   = s * (1.0f / 384.0f);
    float var = q * (1.0f / 384.0f) - m * m;
    float inv = rsqrtf(var + 1e-5f);

    #pragma unroll
    for (int j = 0; j < 3; ++j) {
        int col = j * 128 + lane * 4;
        float4 gq = *(const float4*)(gamma + col);
        float4 bq = *(const float4*)(beta + col);
        float o0 = (v[j].x - m) * inv * gq.x + bq.x;
        float o1 = (v[j].y - m) * inv * gq.y + bq.y;
        float o2 = (v[j].z - m) * inv * gq.z + bq.z;
        float o3 = (v[j].w - m) * inv * gq.w + bq.w;
        __half2 h0 = __floats2half2_rn(o0, o1);
        __half2 h1 = __floats2half2_rn(o2, o3);
        uint32_t u0, u1;
        memcpy(&u0, &h0, 4); memcpy(&u1, &h1, 4);
        uint2 ov; ov.x = u0; ov.y = u1;
        *(uint2*)(yr + col) = ov;
    }
}

// ---------------- driver ----------------
extern "C" void kernel_launch(void* const* d_in, const int* in_sizes, int n_in,
                              void* d_out, int out_size) {
    const float* x_in  = (const float*)d_in[0];
    const float* ln1_g = (const float*)d_in[1];
    const float* ln1_b = (const float*)d_in[2];
    const float* qkv_w = (const float*)d_in[3];
    const float* temp  = (const float*)d_in[4];
    const float* out_w = (const float*)d_in[5];
    const float* out_b = (const float*)d_in[6];
    const float* ln2_g = (const float*)d_in[7];
    const float* ln2_b = (const float*)d_in[8];
    const float* ff_w1 = (const float*)d_in[9];
    const float* ff_b1 = (const float*)d_in[10];
    const float* ff_w2 = (const float*)d_in[11];
    const float* ff_b2 = (const float*)d_in[12];
    float* x = (float*)d_out;

    __half *p_ln, *p_qkv, *p_attn, *p_ff, *p_wh;
    cudaGetSymbolAddress((void**)&p_ln,   g_ln);
    cudaGetSymbolAddress((void**)&p_qkv,  g_qkv);
    cudaGetSymbolAddress((void**)&p_attn, g_attn);
    cudaGetSymbolAddress((void**)&p_ff,   g_ff);
    cudaGetSymbolAddress((void**)&p_wh,   g_wh);

    cudaFuncSetAttribute(mma_gemm<3>, cudaFuncAttributeMaxDynamicSharedMemorySize, GS_BYTES);
    cudaFuncSetAttribute(mma_gemm<2>, cudaFuncAttributeMaxDynamicSharedMemorySize, GS_BYTES);
    cudaFuncSetAttribute(mma_gemm64, cudaFuncAttributeMaxDynamicSharedMemorySize, G6_BYTES);
    cudaFuncSetAttribute(flash_kernel, cudaFuncAttributeMaxDynamicSharedMemorySize, FL_DSMEM);

    cudaMemcpyAsync(x, x_in, (size_t)ROWS * DIMV * sizeof(float),
                    cudaMemcpyDeviceToDevice);

    {
        int n0 = DEPTH * WT_QKV_PER, n1 = DEPTH * WT_WO_PER;
        int n2 = DEPTH * WT_W1_PER;
        int n4tot = WT_TOTAL / 4;
        cvt_all_kernel<<<(n4tot + 255) / 256, 256>>>(
            qkv_w, n0, out_w, n1, ff_w1, n2, ff_w2, p_wh, n4tot);
    }

    for (int l = 0; l < DEPTH; l++) {
        // --- attention block ---
        ln_kernel<<<ROWS / 8, 256>>>(x, ln1_g + l * DIMV, ln1_b + l * DIMV, p_ln);
        mma_gemm<3><<<dim3(QKVW / 128, ROWS / 128), 256, GS_BYTES>>>(
            p_ln, p_wh + WT_QKV_OFF + (size_t)l * WT_QKV_PER,
            nullptr, temp, l, p_qkv, ROWS, QKVW, DIMV);
        flash_kernel<<<dim3(NN / 128, BHN), 256, FL_DSMEM>>>(p_qkv, p_attn);
        mma_gemm64<<<dim3(DIMV / 128, ROWS / 64), 256, G6_BYTES>>>(
            p_attn, p_wh + WT_WO_OFF + (size_t)l * WT_WO_PER,
            out_b + l * DIMV, x, x, ROWS, DIMV, INNER);
        // --- feed-forward block ---
        ln_kernel<<<ROWS / 8, 256>>>(x, ln2_g + l * DIMV, ln2_b + l * DIMV, p_ln);
        mma_gemm<2><<<dim3(MLPV / 128, ROWS / 128), 256, GS_BYTES>>>(
            p_ln, p_wh + WT_W1_OFF + (size_t)l * WT_W1_PER,
            ff_b1 + l * MLPV, nullptr, 0, p_ff, ROWS, MLPV, DIMV);
        mma_gemm64<<<dim3(DIMV / 128, ROWS / 64), 256, G6_BYTES>>>(
            p_ff, p_wh + WT_W2_OFF + (size_t)l * WT_W2_PER,
            ff_b2 + l * DIMV, x, x, ROWS, DIMV, MLPV);
    }
}

// round 16
// speedup vs baseline: 1.0412x; 1.0412x over previous
#include <cuda_runtime.h>
#include <cuda_fp16.h>
#include <math.h>
#include <stdint.h>
#include <string.h>

#define BB     16
#define NN     1024
#define DIMV   384
#define DEPTH  6
#define HEADS  6
#define DH     64
#define INNER  384
#define MLPV   1536
#define ROWS   (BB*NN)       // 16384
#define BHN    (BB*HEADS)    // 96
#define QKVW   (3*INNER)     // 1152
#define NEGMAX -3.4028234663852886e38f

// ---------------- scratch (half precision operands) ----------------
__device__ __half g_ln[(size_t)ROWS * DIMV];
__device__ __half g_qkv[(size_t)ROWS * QKVW];
__device__ __half g_attn[(size_t)ROWS * INNER];
__device__ __half g_ff[(size_t)ROWS * MLPV];
// half copies of weights, NATURAL [K][N] layout
#define WT_QKV_OFF  0
#define WT_QKV_PER  (DIMV*QKVW)
#define WT_WO_OFF   (WT_QKV_OFF + DEPTH*WT_QKV_PER)
#define WT_WO_PER   (INNER*DIMV)
#define WT_W1_OFF   (WT_WO_OFF + DEPTH*WT_WO_PER)
#define WT_W1_PER   (DIMV*MLPV)
#define WT_W2_OFF   (WT_W1_OFF + DEPTH*WT_W1_PER)
#define WT_W2_PER   (MLPV*DIMV)
#define WT_TOTAL    (WT_W2_OFF + DEPTH*WT_W2_PER)
__device__ __half g_wh[(size_t)WT_TOTAL];

// ================= helpers =================
__device__ __forceinline__ uint32_t smem_u32(const void* p) {
    uint32_t r;
    asm("{ .reg .u64 t; cvta.to.shared.u64 t, %1; cvt.u32.u64 %0, t; }" : "=r"(r) : "l"(p));
    return r;
}
__device__ __forceinline__ void cp16(uint32_t dst, const void* src) {
    asm volatile("cp.async.cg.shared.global [%0], [%1], 16;" :: "r"(dst), "l"(src));
}
__device__ __forceinline__ void mma16(float c[4], const uint32_t a[4], const uint32_t b[2]) {
    asm volatile(
        "mma.sync.aligned.m16n8k16.row.col.f32.f16.f16.f32 "
        "{%0,%1,%2,%3}, {%4,%5,%6,%7}, {%8,%9}, {%0,%1,%2,%3};"
        : "+f"(c[0]), "+f"(c[1]), "+f"(c[2]), "+f"(c[3])
        : "r"(a[0]), "r"(a[1]), "r"(a[2]), "r"(a[3]), "r"(b[0]), "r"(b[1]));
}
__device__ __forceinline__ void ldm_x4(uint32_t r[4], uint32_t a) {
    asm volatile("ldmatrix.sync.aligned.m8n8.x4.shared.b16 {%0,%1,%2,%3}, [%4];"
                 : "=r"(r[0]), "=r"(r[1]), "=r"(r[2]), "=r"(r[3]) : "r"(a));
}
__device__ __forceinline__ void ldm_x2(uint32_t r[2], uint32_t a) {
    asm volatile("ldmatrix.sync.aligned.m8n8.x2.shared.b16 {%0,%1}, [%2];"
                 : "=r"(r[0]), "=r"(r[1]) : "r"(a));
}
__device__ __forceinline__ void ldm_x2t(uint32_t r[2], uint32_t a) {
    asm volatile("ldmatrix.sync.aligned.m8n8.x2.trans.shared.b16 {%0,%1}, [%2];"
                 : "=r"(r[0]), "=r"(r[1]) : "r"(a));
}
__device__ __forceinline__ uint32_t packh2(float x, float y) {
    __half2 h = __floats2half2_rn(x, y);
    uint32_t u;
    memcpy(&u, &h, 4);
    return u;
}

// ================= dense fp16 GEMM, 128x128 tile ====================
// EPI 1: C(f32) = res + AB + bias
// EPI 2: C(half) = gelu(AB + bias)
// EPI 3: C(half) = AB with q-columns (col < INNER) scaled by exp(temp[layer])
#define GS_A_B      18432u
#define GS_STAGE_B  35840u
#define GS_BYTES    (3u * GS_STAGE_B)         // 107520 B
template <int EPI>
__global__ void __launch_bounds__(256, 2) mma_gemm(
    const __half* __restrict__ A, const __half* __restrict__ Bw,
    const float* __restrict__ bias, const float* __restrict__ res,
    const float* __restrict__ temp, int layer,
    void* __restrict__ Cv, int M, int Nn, int K) {
    extern __shared__ __align__(16) char smraw[];
    const int tid = threadIdx.x;
    const int wid = tid >> 5, lane = tid & 31;
    const int g = lane >> 2, tg = lane & 3;
    const int l16 = lane & 15;
    const int wm = (wid & 1) * 64, wn = (wid >> 1) * 32;
    const int m0 = blockIdx.y * 128, n0 = blockIdx.x * 128;

    float qs = 1.0f;
    if (EPI == 3) qs = expf(temp[layer]);

    float c[4][4][4];
    #pragma unroll
    for (int mt = 0; mt < 4; ++mt)
        #pragma unroll
        for (int nt = 0; nt < 4; ++nt)
            #pragma unroll
            for (int k = 0; k < 4; ++k) c[mt][nt][k] = 0.0f;

    const int nc = K >> 6;
    const uint32_t sbase = smem_u32(smraw);

    auto issue = [&](int ci) {
        uint32_t base = sbase + (uint32_t)(ci % 3) * GS_STAGE_B;
        int kt = ci << 6;
        #pragma unroll
        for (int i = 0; i < 4; ++i) {
            int f = tid + i * 256;
            int r = f >> 3, c8 = (f & 7) << 3;
            cp16(base + (uint32_t)(r * 72 + c8) * 2u,
                 A + (size_t)(m0 + r) * K + kt + c8);
        }
        #pragma unroll
        for (int i = 0; i < 4; ++i) {
            int f = tid + i * 256;
            int r = f >> 4, c8 = (f & 15) << 3;
            cp16(base + GS_A_B + (uint32_t)(r * 136 + c8) * 2u,
                 Bw + (size_t)(kt + r) * Nn + n0 + c8);
        }
        asm volatile("cp.async.commit_group;" ::: "memory");
    };

    issue(0);
    issue(1);

    for (int ci = 0; ci < nc; ++ci) {
        asm volatile("cp.async.wait_group 1;" ::: "memory");
        __syncthreads();
        if (ci + 2 < nc) {
            issue(ci + 2);
        } else {
            asm volatile("cp.async.commit_group;" ::: "memory");
        }

        const uint32_t stA = sbase + (uint32_t)(ci % 3) * GS_STAGE_B;
        const uint32_t stB = stA + GS_A_B;
        #pragma unroll
        for (int ks = 0; ks < 4; ++ks) {
            uint32_t af[4][4], bf[4][2];
            #pragma unroll
            for (int mt = 0; mt < 4; ++mt)
                ldm_x4(af[mt], stA + (uint32_t)((wm + mt * 16 + l16) * 72
                                                + ks * 16 + (lane >> 4) * 8) * 2u);
            #pragma unroll
            for (int nt = 0; nt < 4; ++nt)
                ldm_x2t(bf[nt], stB + (uint32_t)((ks * 16 + l16) * 136
                                                 + wn + nt * 8) * 2u);
            #pragma unroll
            for (int mt = 0; mt < 4; ++mt)
                #pragma unroll
                for (int nt = 0; nt < 4; ++nt)
                    mma16(c[mt][nt], af[mt], bf[nt]);
        }
    }

    #pragma unroll
    for (int mt = 0; mt < 4; ++mt) {
        #pragma unroll
        for (int nt = 0; nt < 4; ++nt) {
            int col = n0 + wn + nt * 8 + 2 * tg;
            float sc = (EPI == 3 && col < INNER) ? qs : 1.0f;
            #pragma unroll
            for (int h = 0; h < 2; ++h) {
                int row = m0 + wm + mt * 16 + g + h * 8;
                float v0 = c[mt][nt][h * 2 + 0];
                float v1 = c[mt][nt][h * 2 + 1];
                if (EPI == 1 || EPI == 2) { v0 += bias[col]; v1 += bias[col + 1]; }
                if (EPI == 1) {
                    float2 r2 = *(const float2*)(res + (size_t)row * Nn + col);
                    v0 += r2.x; v1 += r2.y;
                    *(float2*)((float*)Cv + (size_t)row * Nn + col) = make_float2(v0, v1);
                } else {
                    if (EPI == 2) {
                        v0 = 0.5f * v0 * (1.0f + erff(v0 * 0.70710678118654752f));
                        v1 = 0.5f * v1 * (1.0f + erff(v1 * 0.70710678118654752f));
                    }
                    if (EPI == 3) { v0 *= sc; v1 *= sc; }
                    *(__half2*)((__half*)Cv + (size_t)row * Nn + col) =
                        __floats2half2_rn(v0, v1);
                }
            }
        }
    }
}

// ================= flash attention: pre-scaled Q, no-max softmax (R15 version) =====
#define FL_PS_H    (128 * 72)
#define FL_KV_H    (64 * 72)
#define FL_TOT_H   (FL_PS_H + 6 * FL_KV_H)    // 36864
#define FL_DSMEM   (FL_TOT_H * 2)             // 73728 B
__global__ void __launch_bounds__(256, 2) flash_kernel(
    const __half* __restrict__ qkv,
    __half* __restrict__ o) {
    extern __shared__ __align__(16) __half fsh[];

    int bh = blockIdx.y;
    int b = bh / HEADS, h = bh - b * HEADS;
    int rt = blockIdx.x * 128;
    int tid = threadIdx.x, wid = tid >> 5, lane = tid & 31;
    int g = lane >> 2, tg = lane & 3;
    int l16 = lane & 15;

    const __half* qb = qkv + (size_t)b * NN * QKVW + h * DH;
    const __half* kb = qb + INNER;
    const __half* vb = qb + 2 * INNER;
    const uint32_t sbase = smem_u32(fsh);

    #pragma unroll
    for (int i = 0; i < 4; ++i) {
        int f = tid + i * 256;
        int r = f >> 3, c8 = (f & 7) << 3;
        *(uint4*)&fsh[r * 72 + c8] = *(const uint4*)(qb + (size_t)(rt + r) * QKVW + c8);
    }
    auto issue_kv = [&](int i) {
        uint32_t kbb = sbase + (uint32_t)(FL_PS_H + (i % 3) * 2 * FL_KV_H) * 2u;
        uint32_t vbb = kbb + FL_KV_H * 2u;
        int kt = i << 6;
        #pragma unroll
        for (int it = 0; it < 2; ++it) {
            int f = tid + it * 256;
            int r = f >> 3, c8 = (f & 7) << 3;
            cp16(kbb + (uint32_t)(r * 72 + c8) * 2u, kb + (size_t)(kt + r) * QKVW + c8);
            cp16(vbb + (uint32_t)(r * 72 + c8) * 2u, vb + (size_t)(kt + r) * QKVW + c8);
        }
        asm volatile("cp.async.commit_group;" ::: "memory");
    };
    issue_kv(0);
    issue_kv(1);
    __syncthreads();

    uint32_t qf[4][4];
    #pragma unroll
    for (int ks = 0; ks < 4; ++ks)
        ldm_x4(qf[ks], sbase + (uint32_t)((wid * 16 + l16) * 72
                                          + ks * 16 + (lane >> 4) * 8) * 2u);

    float l0 = 0.0f, l1 = 0.0f;
    float oacc[8][4];
    #pragma unroll
    for (int nt = 0; nt < 8; ++nt)
        #pragma unroll
        for (int k = 0; k < 4; ++k) oacc[nt][k] = 0.0f;

    const int gi0 = rt + wid * 16 + g;
    const int gi1 = gi0 + 8;

    for (int i = 0; i < NN / 64; ++i) {
        asm volatile("cp.async.wait_group 1;" ::: "memory");
        __syncthreads();
        if (i + 2 < NN / 64) {
            issue_kv(i + 2);
        } else {
            asm volatile("cp.async.commit_group;" ::: "memory");
        }

        const uint32_t kbb = sbase + (uint32_t)(FL_PS_H + (i % 3) * 2 * FL_KV_H) * 2u;
        const uint32_t vbb = kbb + FL_KV_H * 2u;
        const int kt = i << 6;

        float s[8][4];
        #pragma unroll
        for (int nt = 0; nt < 8; ++nt)
            #pragma unroll
            for (int k = 0; k < 4; ++k) s[nt][k] = 0.0f;
        #pragma unroll
        for (int ks = 0; ks < 4; ++ks) {
            #pragma unroll
            for (int nt = 0; nt < 8; ++nt) {
                uint32_t bf[2];
                ldm_x2(bf, kbb + (uint32_t)((nt * 8 + (l16 & 7)) * 72
                                            + ks * 16 + (l16 >> 3) * 8) * 2u);
                mma16(s[nt], qf[ks], bf);
            }
        }
        float sum0 = 0.0f, sum1 = 0.0f;
        #pragma unroll
        for (int nt = 0; nt < 8; ++nt) {
            int gj = kt + nt * 8 + 2 * tg;
            s[nt][0] = (gi0 == gj)     ? 0.0f : __expf(s[nt][0]);
            s[nt][1] = (gi0 == gj + 1) ? 0.0f : __expf(s[nt][1]);
            s[nt][2] = (gi1 == gj)     ? 0.0f : __expf(s[nt][2]);
            s[nt][3] = (gi1 == gj + 1) ? 0.0f : __expf(s[nt][3]);
            sum0 += s[nt][0] + s[nt][1];
            sum1 += s[nt][2] + s[nt][3];
        }
        sum0 += __shfl_xor_sync(0xffffffffu, sum0, 1);
        sum0 += __shfl_xor_sync(0xffffffffu, sum0, 2);
        sum1 += __shfl_xor_sync(0xffffffffu, sum1, 1);
        sum1 += __shfl_xor_sync(0xffffffffu, sum1, 2);
        l0 += sum0;
        l1 += sum1;
        #pragma unroll
        for (int ks = 0; ks < 4; ++ks) {
            uint32_t pf[4];
            pf[0] = packh2(s[2 * ks][0],     s[2 * ks][1]);
            pf[1] = packh2(s[2 * ks][2],     s[2 * ks][3]);
            pf[2] = packh2(s[2 * ks + 1][0], s[2 * ks + 1][1]);
            pf[3] = packh2(s[2 * ks + 1][2], s[2 * ks + 1][3]);
            #pragma unroll
            for (int nt = 0; nt < 8; ++nt) {
                uint32_t bf[2];
                ldm_x2t(bf, vbb + (uint32_t)((ks * 16 + l16) * 72 + nt * 8) * 2u);
                mma16(oacc[nt], pf, bf);
            }
        }
    }

    float inv0 = 1.0f / l0, inv1 = 1.0f / l1;
    #pragma unroll
    for (int nt = 0; nt < 8; ++nt) {
        int gc = h * DH + nt * 8 + 2 * tg;
        int gr0 = b * NN + gi0;
        int gr1 = b * NN + gi1;
        *(__half2*)(o + (size_t)gr0 * INNER + gc) =
            __floats2half2_rn(oacc[nt][0] * inv0, oacc[nt][1] * inv0);
        *(__half2*)(o + (size_t)gr1 * INNER + gc) =
            __floats2half2_rn(oacc[nt][2] * inv1, oacc[nt][3] * inv1);
    }
}

// ---------------- fused fp32 -> half convert ----------------
__global__ void cvt_all_kernel(const float* __restrict__ s0, int n0,
                               const float* __restrict__ s1, int n1,
                               const float* __restrict__ s2, int n2,
                               const float* __restrict__ s3,
                               __half* __restrict__ dst, int n4tot) {
    int i = blockIdx.x * blockDim.x + threadIdx.x;
    if (i >= n4tot) return;
    int e = i * 4;
    const float* src;
    if (e < n0)                 { src = s0 + e; }
    else if (e < n0 + n1)       { src = s1 + (e - n0); }
    else if (e < n0 + n1 + n2)  { src = s2 + (e - n0 - n1); }
    else                        { src = s3 + (e - n0 - n1 - n2); }
    float4 v = *(const float4*)src;
    __half2 h0 = __floats2half2_rn(v.x, v.y);
    __half2 h1 = __floats2half2_rn(v.z, v.w);
    uint32_t u0, u1;
    memcpy(&u0, &h0, 4); memcpy(&u1, &h1, 4);
    uint2 ov; ov.x = u0; ov.y = u1;
    *(uint2*)(dst + (size_t)e) = ov;
}

// ---------------- LayerNorm: one WARP per row ----------------
__global__ void ln_kernel(const float* __restrict__ x,
                          const float* __restrict__ gamma,
                          const float* __restrict__ beta,
                          __half* __restrict__ y) {
    int wid = threadIdx.x >> 5, lane = threadIdx.x & 31;
    int row = blockIdx.x * 8 + wid;
    const float* xr = x + (size_t)row * DIMV;
    __half*      yr = y + (size_t)row * DIMV;

    float4 v[3];
    #pragma unroll
    for (int j = 0; j < 3; ++j)
        v[j] = *(const float4*)(xr + j * 128 + lane * 4);

    float s = 0.0f, q = 0.0f;
    #pragma unroll
    for (int j = 0; j < 3; ++j) {
        s += v[j].x + v[j].y + v[j].z + v[j].w;
        q += v[j].x * v[j].x + v[j].y * v[j].y + v[j].z * v[j].z + v[j].w * v[j].w;
    }
    #pragma unroll
    for (int o = 16; o > 0; o >>= 1) {
        s += __shfl_xor_sync(0xffffffffu, s, o);
        q += __shfl_xor_sync(0xffffffffu, q, o);
    }
    float m   = s * (1.0f / 384.0f);
    float var = q * (1.0f / 384.0f) - m * m;
    float inv = rsqrtf(var + 1e-5f);

    #pragma unroll
    for (int j = 0; j < 3; ++j) {
        int col = j * 128 + lane * 4;
        float4 gq = *(const float4*)(gamma + col);
        float4 bq = *(const float4*)(beta + col);
        float o0 = (v[j].x - m) * inv * gq.x + bq.x;
        float o1 = (v[j].y - m) * inv * gq.y + bq.y;
        float o2 = (v[j].z - m) * inv * gq.z + bq.z;
        float o3 = (v[j].w - m) * inv * gq.w + bq.w;
        __half2 h0 = __floats2half2_rn(o0, o1);
        __half2 h1 = __floats2half2_rn(o2, o3);
        uint32_t u0, u1;
        memcpy(&u0, &h0, 4); memcpy(&u1, &h1, 4);
        uint2 ov; ov.x = u0; ov.y = u1;
        *(uint2*)(yr + col) = ov;
    }
}

// ---------------- driver ----------------
extern "C" void kernel_launch(void* const* d_in, const int* in_sizes, int n_in,
                              void* d_out, int out_size) {
    const float* x_in  = (const float*)d_in[0];
    const float* ln1_g = (const float*)d_in[1];
    const float* ln1_b = (const float*)d_in[2];
    const float* qkv_w = (const float*)d_in[3];
    const float* temp  = (const float*)d_in[4];
    const float* out_w = (const float*)d_in[5];
    const float* out_b = (const float*)d_in[6];
    const float* ln2_g = (const float*)d_in[7];
    const float* ln2_b = (const float*)d_in[8];
    const float* ff_w1 = (const float*)d_in[9];
    const float* ff_b1 = (const float*)d_in[10];
    const float* ff_w2 = (const float*)d_in[11];
    const float* ff_b2 = (const float*)d_in[12];
    float* x = (float*)d_out;

    __half *p_ln, *p_qkv, *p_attn, *p_ff, *p_wh;
    cudaGetSymbolAddress((void**)&p_ln,   g_ln);
    cudaGetSymbolAddress((void**)&p_qkv,  g_qkv);
    cudaGetSymbolAddress((void**)&p_attn, g_attn);
    cudaGetSymbolAddress((void**)&p_ff,   g_ff);
    cudaGetSymbolAddress((void**)&p_wh,   g_wh);

    cudaFuncSetAttribute(mma_gemm<1>, cudaFuncAttributeMaxDynamicSharedMemorySize, GS_BYTES);
    cudaFuncSetAttribute(mma_gemm<2>, cudaFuncAttributeMaxDynamicSharedMemorySize, GS_BYTES);
    cudaFuncSetAttribute(mma_gemm<3>, cudaFuncAttributeMaxDynamicSharedMemorySize, GS_BYTES);
    cudaFuncSetAttribute(flash_kernel, cudaFuncAttributeMaxDynamicSharedMemorySize, FL_DSMEM);

    cudaMemcpyAsync(x, x_in, (size_t)ROWS * DIMV * sizeof(float),
                    cudaMemcpyDeviceToDevice);

    {
        int n0 = DEPTH * WT_QKV_PER, n1 = DEPTH * WT_WO_PER;
        int n2 = DEPTH * WT_W1_PER;
        int n4tot = WT_TOTAL / 4;
        cvt_all_kernel<<<(n4tot + 255) / 256, 256>>>(
            qkv_w, n0, out_w, n1, ff_w1, n2, ff_w2, p_wh, n4tot);
    }

    for (int l = 0; l < DEPTH; l++) {
        // --- attention block ---
        ln_kernel<<<ROWS / 8, 256>>>(x, ln1_g + l * DIMV, ln1_b + l * DIMV, p_ln);
        mma_gemm<3><<<dim3(QKVW / 128, ROWS / 128), 256, GS_BYTES>>>(
            p_ln, p_wh + WT_QKV_OFF + (size_t)l * WT_QKV_PER,
            nullptr, nullptr, temp, l, p_qkv, ROWS, QKVW, DIMV);
        flash_kernel<<<dim3(NN / 128, BHN), 256, FL_DSMEM>>>(p_qkv, p_attn);
        mma_gemm<1><<<dim3(DIMV / 128, ROWS / 128), 256, GS_BYTES>>>(
            p_attn, p_wh + WT_WO_OFF + (size_t)l * WT_WO_PER,
            out_b + l * DIMV, x, nullptr, 0, x, ROWS, DIMV, INNER);
        // --- feed-forward block ---
        ln_kernel<<<ROWS / 8, 256>>>(x, ln2_g + l * DIMV, ln2_b + l * DIMV, p_ln);
        mma_gemm<2><<<dim3(MLPV / 128, ROWS / 128), 256, GS_BYTES>>>(
            p_ln, p_wh + WT_W1_OFF + (size_t)l * WT_W1_PER,
            ff_b1 + l * MLPV, nullptr, nullptr, 0, p_ff, ROWS, MLPV, DIMV);
        mma_gemm<1><<<dim3(DIMV / 128, ROWS / 128), 256, GS_BYTES>>>(
            p_ff, p_wh + WT_W2_OFF + (size_t)l * WT_W2_PER,
            ff_b2 + l * DIMV, x, nullptr, 0, x, ROWS, DIMV, MLPV);
    }
}